// round 1
// baseline (speedup 1.0000x reference)
#include <cuda_runtime.h>
#include <cuda_bf16.h>
#include <math.h>

#define D_MODEL 2048
#define N_HEADS 16
#define HEAD_DIM 128
#define MLP_DIM 8192
#define BATCH 2
#define SEQ 2048
#define TOK (BATCH * SEQ)

// ---------------- scratch (static device globals; no allocation allowed) ----
__device__ float g_h[(size_t)TOK * D_MODEL];    // rmsnorm output (reused)
__device__ float g_q[(size_t)TOK * D_MODEL];
__device__ float g_k[(size_t)TOK * D_MODEL];
__device__ float g_v[(size_t)TOK * D_MODEL];
__device__ float g_att[(size_t)TOK * D_MODEL];
__device__ float g_x1[(size_t)TOK * D_MODEL];   // x after attention residual
__device__ float g_up[(size_t)TOK * MLP_DIM];   // gelu(h @ w_up^T)

// ---------------- RMSNorm ---------------------------------------------------
__global__ void rmsnorm_kernel(const float* __restrict__ x,
                               const float* __restrict__ w,
                               float* __restrict__ out) {
    int row = blockIdx.x;
    const float4* xr = reinterpret_cast<const float4*>(x + (size_t)row * D_MODEL);
    const float4* w4 = reinterpret_cast<const float4*>(w);
    float4* o4 = reinterpret_cast<float4*>(out + (size_t)row * D_MODEL);

    float ss = 0.f;
    for (int i = threadIdx.x; i < D_MODEL / 4; i += blockDim.x) {
        float4 v = xr[i];
        ss += v.x * v.x + v.y * v.y + v.z * v.z + v.w * v.w;
    }
    // warp reduce
    for (int off = 16; off > 0; off >>= 1)
        ss += __shfl_xor_sync(0xFFFFFFFFu, ss, off);

    __shared__ float red[8];
    __shared__ float s_rms;
    int lane = threadIdx.x & 31, wid = threadIdx.x >> 5;
    if (lane == 0) red[wid] = ss;
    __syncthreads();
    if (threadIdx.x == 0) {
        float t = 0.f;
        #pragma unroll
        for (int i = 0; i < 8; i++) t += red[i];
        s_rms = rsqrtf(t / (float)D_MODEL + 1e-6f);
    }
    __syncthreads();
    float r = s_rms;
    for (int i = threadIdx.x; i < D_MODEL / 4; i += blockDim.x) {
        float4 v = xr[i];
        float4 ww = w4[i];
        o4[i] = make_float4(v.x * r * ww.x, v.y * r * ww.y,
                            v.z * r * ww.z, v.w * r * ww.w);
    }
}

// ---------------- SGEMM: C[M,N] = A[M,K] @ B[N,K]^T  (+epilogue) ------------
// EPI: 0 = plain store, 1 = exact gelu, 2 = RES + acc
#define BM 128
#define BN 128
#define BKK 8

template <int EPI>
__global__ void __launch_bounds__(256)
sgemm_nt(int M, int N, int K,
         const float* __restrict__ A, const float* __restrict__ B,
         const float* __restrict__ RES, float* __restrict__ C) {
    __shared__ float As[BKK][BM];
    __shared__ float Bs[BKK][BN];

    int t = threadIdx.x;
    int m0 = blockIdx.y * BM;
    int n0 = blockIdx.x * BN;
    int tx = t & 15, ty = t >> 4;

    float acc[8][8];
    #pragma unroll
    for (int i = 0; i < 8; i++)
        #pragma unroll
        for (int j = 0; j < 8; j++) acc[i][j] = 0.f;

    int lrow = t >> 1;            // 0..127
    int lcol = (t & 1) * 4;       // 0 or 4
    const float* Aptr = A + (size_t)(m0 + lrow) * K + lcol;
    const float* Bptr = B + (size_t)(n0 + lrow) * K + lcol;

    for (int k0 = 0; k0 < K; k0 += BKK) {
        float4 av = *reinterpret_cast<const float4*>(Aptr + k0);
        float4 bv = *reinterpret_cast<const float4*>(Bptr + k0);
        __syncthreads();
        As[lcol + 0][lrow] = av.x; As[lcol + 1][lrow] = av.y;
        As[lcol + 2][lrow] = av.z; As[lcol + 3][lrow] = av.w;
        Bs[lcol + 0][lrow] = bv.x; Bs[lcol + 1][lrow] = bv.y;
        Bs[lcol + 2][lrow] = bv.z; Bs[lcol + 3][lrow] = bv.w;
        __syncthreads();

        #pragma unroll
        for (int kk = 0; kk < BKK; kk++) {
            float4 a0 = *reinterpret_cast<const float4*>(&As[kk][ty * 8]);
            float4 a1 = *reinterpret_cast<const float4*>(&As[kk][ty * 8 + 4]);
            float4 b0 = *reinterpret_cast<const float4*>(&Bs[kk][tx * 8]);
            float4 b1 = *reinterpret_cast<const float4*>(&Bs[kk][tx * 8 + 4]);
            float ar[8] = {a0.x, a0.y, a0.z, a0.w, a1.x, a1.y, a1.z, a1.w};
            float br[8] = {b0.x, b0.y, b0.z, b0.w, b1.x, b1.y, b1.z, b1.w};
            #pragma unroll
            for (int i = 0; i < 8; i++)
                #pragma unroll
                for (int j = 0; j < 8; j++)
                    acc[i][j] = fmaf(ar[i], br[j], acc[i][j]);
        }
    }

    #pragma unroll
    for (int i = 0; i < 8; i++) {
        size_t roff = (size_t)(m0 + ty * 8 + i) * N + n0 + tx * 8;
        float v[8];
        #pragma unroll
        for (int j = 0; j < 8; j++) v[j] = acc[i][j];
        if (EPI == 1) {
            #pragma unroll
            for (int j = 0; j < 8; j++)
                v[j] = 0.5f * v[j] * (1.0f + erff(v[j] * 0.70710678118654752f));
        } else if (EPI == 2) {
            float4 r0 = *reinterpret_cast<const float4*>(RES + roff);
            float4 r1 = *reinterpret_cast<const float4*>(RES + roff + 4);
            v[0] += r0.x; v[1] += r0.y; v[2] += r0.z; v[3] += r0.w;
            v[4] += r1.x; v[5] += r1.y; v[6] += r1.z; v[7] += r1.w;
        }
        *reinterpret_cast<float4*>(C + roff)     = make_float4(v[0], v[1], v[2], v[3]);
        *reinterpret_cast<float4*>(C + roff + 4) = make_float4(v[4], v[5], v[6], v[7]);
    }
}

// ---------------- Flash attention (fp32, causal, key mask) ------------------
#define BQ 64
#define BKV 64
#define SS_LD 65  // padded leading dim for the score tile

// dynamic smem: Qs[64*128] Ks[64*128] Vs[64*128] Ss[64*65] m[64] l[64] alpha[64]
#define FA_SMEM_FLOATS (3 * BQ * HEAD_DIM + BQ * SS_LD + 3 * BQ)
#define FA_SMEM_BYTES  (FA_SMEM_FLOATS * 4)

__global__ void __launch_bounds__(256)
flash_attn_kernel(const float* __restrict__ Q, const float* __restrict__ K,
                  const float* __restrict__ V, const int* __restrict__ mask,
                  float* __restrict__ O) {
    extern __shared__ float sm[];
    float* Qs = sm;
    float* Ks = Qs + BQ * HEAD_DIM;
    float* Vs = Ks + BQ * HEAD_DIM;
    float* Ss = Vs + BQ * HEAD_DIM;
    float* m_s = Ss + BQ * SS_LD;
    float* l_s = m_s + BQ;
    float* alpha_s = l_s + BQ;

    int qi = blockIdx.x;
    int h  = blockIdx.y;
    int b  = blockIdx.z;
    int t  = threadIdx.x;
    int tx = t & 15, ty = t >> 4;
    int q0 = qi * BQ;
    size_t base = (size_t)b * SEQ * D_MODEL + (size_t)h * HEAD_DIM;
    const int* bmask = mask + b * SEQ;
    const float scale = 0.08838834764831845f;  // 1/sqrt(128)

    // load Q tile (64 x 128) as float4
    for (int i = t; i < BQ * (HEAD_DIM / 4); i += 256) {
        int r = i >> 5, c4 = i & 31;
        reinterpret_cast<float4*>(Qs)[i] = *reinterpret_cast<const float4*>(
            Q + base + (size_t)(q0 + r) * D_MODEL + c4 * 4);
    }
    if (t < BQ) { m_s[t] = -3.0e38f; l_s[t] = 0.f; }

    float acc[4][8];
    #pragma unroll
    for (int r = 0; r < 4; r++)
        #pragma unroll
        for (int c = 0; c < 8; c++) acc[r][c] = 0.f;

    for (int j = 0; j <= qi; ++j) {
        int k0 = j * BKV;
        __syncthreads();  // previous PV stage done before overwriting K/V
        for (int i = t; i < BKV * (HEAD_DIM / 4); i += 256) {
            int r = i >> 5, c4 = i & 31;
            size_t goff = base + (size_t)(k0 + r) * D_MODEL + c4 * 4;
            reinterpret_cast<float4*>(Ks)[i] = *reinterpret_cast<const float4*>(K + goff);
            reinterpret_cast<float4*>(Vs)[i] = *reinterpret_cast<const float4*>(V + goff);
        }
        __syncthreads();

        // scores: each thread 4 rows x 4 cols
        float s[4][4];
        #pragma unroll
        for (int r = 0; r < 4; r++)
            #pragma unroll
            for (int c = 0; c < 4; c++) s[r][c] = 0.f;

        for (int d = 0; d < HEAD_DIM; d += 4) {
            float4 qv[4], kv[4];
            #pragma unroll
            for (int r = 0; r < 4; r++)
                qv[r] = *reinterpret_cast<const float4*>(&Qs[(ty * 4 + r) * HEAD_DIM + d]);
            #pragma unroll
            for (int c = 0; c < 4; c++)
                kv[c] = *reinterpret_cast<const float4*>(&Ks[(tx * 4 + c) * HEAD_DIM + d]);
            #pragma unroll
            for (int r = 0; r < 4; r++)
                #pragma unroll
                for (int c = 0; c < 4; c++)
                    s[r][c] += qv[r].x * kv[c].x + qv[r].y * kv[c].y +
                               qv[r].z * kv[c].z + qv[r].w * kv[c].w;
        }

        bool diag = (j == qi);
        #pragma unroll
        for (int r = 0; r < 4; r++) {
            int qg = q0 + ty * 4 + r;
            #pragma unroll
            for (int c = 0; c < 4; c++) {
                int kg = k0 + tx * 4 + c;
                float v = s[r][c] * scale;
                if ((diag && kg > qg) || bmask[kg] == 0) v = -1e9f;
                Ss[(ty * 4 + r) * SS_LD + tx * 4 + c] = v;
            }
        }
        __syncthreads();

        // online softmax: 4 threads per row
        {
            int row = t >> 2, part = t & 3;
            float* srow = &Ss[row * SS_LD + part * 16];
            float vals[16];
            float mx = -3.0e38f;
            #pragma unroll
            for (int i2 = 0; i2 < 16; i2++) { vals[i2] = srow[i2]; mx = fmaxf(mx, vals[i2]); }
            mx = fmaxf(mx, __shfl_xor_sync(0xFFFFFFFFu, mx, 1));
            mx = fmaxf(mx, __shfl_xor_sync(0xFFFFFFFFu, mx, 2));
            float m_old = m_s[row];
            float m_new = fmaxf(m_old, mx);
            float sum = 0.f;
            #pragma unroll
            for (int i2 = 0; i2 < 16; i2++) {
                float p = expf(vals[i2] - m_new);
                srow[i2] = p;
                sum += p;
            }
            sum += __shfl_xor_sync(0xFFFFFFFFu, sum, 1);
            sum += __shfl_xor_sync(0xFFFFFFFFu, sum, 2);
            if (part == 0) {
                float al = expf(m_old - m_new);
                alpha_s[row] = al;
                l_s[row] = l_s[row] * al + sum;
                m_s[row] = m_new;
            }
        }
        __syncthreads();

        // O update: P (64x64) @ V (64x128); thread owns 4 rows x 8 cols
        {
            float al[4];
            #pragma unroll
            for (int r = 0; r < 4; r++) al[r] = alpha_s[ty * 4 + r];
            #pragma unroll
            for (int r = 0; r < 4; r++)
                #pragma unroll
                for (int c = 0; c < 8; c++) acc[r][c] *= al[r];

            for (int k = 0; k < BKV; k++) {
                float4 v0 = *reinterpret_cast<const float4*>(&Vs[k * HEAD_DIM + tx * 8]);
                float4 v1 = *reinterpret_cast<const float4*>(&Vs[k * HEAD_DIM + tx * 8 + 4]);
                #pragma unroll
                for (int r = 0; r < 4; r++) {
                    float p = Ss[(ty * 4 + r) * SS_LD + k];
                    acc[r][0] = fmaf(p, v0.x, acc[r][0]);
                    acc[r][1] = fmaf(p, v0.y, acc[r][1]);
                    acc[r][2] = fmaf(p, v0.z, acc[r][2]);
                    acc[r][3] = fmaf(p, v0.w, acc[r][3]);
                    acc[r][4] = fmaf(p, v1.x, acc[r][4]);
                    acc[r][5] = fmaf(p, v1.y, acc[r][5]);
                    acc[r][6] = fmaf(p, v1.z, acc[r][6]);
                    acc[r][7] = fmaf(p, v1.w, acc[r][7]);
                }
            }
        }
    }
    __syncthreads();

    #pragma unroll
    for (int r = 0; r < 4; r++) {
        int row = ty * 4 + r;
        float l = l_s[row];
        float inv = (l > 0.f) ? (1.f / l) : 0.f;
        size_t ooff = base + (size_t)(q0 + row) * D_MODEL + tx * 8;
        *reinterpret_cast<float4*>(O + ooff) =
            make_float4(acc[r][0] * inv, acc[r][1] * inv, acc[r][2] * inv, acc[r][3] * inv);
        *reinterpret_cast<float4*>(O + ooff + 4) =
            make_float4(acc[r][4] * inv, acc[r][5] * inv, acc[r][6] * inv, acc[r][7] * inv);
    }
}

// ---------------- launch -----------------------------------------------------
extern "C" void kernel_launch(void* const* d_in, const int* in_sizes, int n_in,
                              void* d_out, int out_size) {
    const float* x           = (const float*)d_in[0];
    const int*   attn_mask   = (const int*)  d_in[1];
    const float* w_norm_attn = (const float*)d_in[2];
    const float* wq          = (const float*)d_in[3];
    const float* wk          = (const float*)d_in[4];
    const float* wv          = (const float*)d_in[5];
    const float* wo          = (const float*)d_in[6];
    const float* w_norm_mlp  = (const float*)d_in[7];
    const float* w_up        = (const float*)d_in[8];
    const float* w_down      = (const float*)d_in[9];
    float* out = (float*)d_out;

    float *h, *q, *k, *v, *att, *x1, *up;
    cudaGetSymbolAddress((void**)&h,   g_h);
    cudaGetSymbolAddress((void**)&q,   g_q);
    cudaGetSymbolAddress((void**)&k,   g_k);
    cudaGetSymbolAddress((void**)&v,   g_v);
    cudaGetSymbolAddress((void**)&att, g_att);
    cudaGetSymbolAddress((void**)&x1,  g_x1);
    cudaGetSymbolAddress((void**)&up,  g_up);

    cudaFuncSetAttribute(flash_attn_kernel,
                         cudaFuncAttributeMaxDynamicSharedMemorySize, FA_SMEM_BYTES);

    // 1) rmsnorm(x) -> h
    rmsnorm_kernel<<<TOK, 256>>>(x, w_norm_attn, h);

    // 2) q, k, v projections
    dim3 gD(D_MODEL / BN, TOK / BM);
    sgemm_nt<0><<<gD, 256>>>(TOK, D_MODEL, D_MODEL, h, wq, nullptr, q);
    sgemm_nt<0><<<gD, 256>>>(TOK, D_MODEL, D_MODEL, h, wk, nullptr, k);
    sgemm_nt<0><<<gD, 256>>>(TOK, D_MODEL, D_MODEL, h, wv, nullptr, v);

    // 3) attention
    dim3 gA(SEQ / BQ, N_HEADS, BATCH);
    flash_attn_kernel<<<gA, 256, FA_SMEM_BYTES>>>(q, k, v, attn_mask, att);

    // 4) output projection + residual -> x1
    sgemm_nt<2><<<gD, 256>>>(TOK, D_MODEL, D_MODEL, att, wo, x, x1);

    // 5) rmsnorm(x1) -> h
    rmsnorm_kernel<<<TOK, 256>>>(x1, w_norm_mlp, h);

    // 6) up projection + exact gelu -> up
    dim3 gU(MLP_DIM / BN, TOK / BM);
    sgemm_nt<1><<<gU, 256>>>(TOK, MLP_DIM, D_MODEL, h, w_up, nullptr, up);

    // 7) down projection + residual -> out
    sgemm_nt<2><<<gD, 256>>>(TOK, D_MODEL, MLP_DIM, up, w_down, x1, out);
}

// round 3
// speedup vs baseline: 1.5087x; 1.5087x over previous
#include <cuda_runtime.h>
#include <cuda_bf16.h>
#include <math.h>
#include <stdint.h>

#define D_MODEL 2048
#define N_HEADS 16
#define HEAD_DIM 128
#define MLP_DIM 8192
#define BATCH 2
#define SEQ 2048
#define TOK (BATCH * SEQ)

// ---------------- scratch (static device globals; no allocation allowed) ----
__device__ float g_h[(size_t)TOK * D_MODEL];
__device__ float g_q[(size_t)TOK * D_MODEL];
__device__ float g_k[(size_t)TOK * D_MODEL];
__device__ float g_v[(size_t)TOK * D_MODEL];
__device__ float g_att[(size_t)TOK * D_MODEL];
__device__ float g_x1[(size_t)TOK * D_MODEL];
__device__ float g_up[(size_t)TOK * MLP_DIM];

// ================= warp-MMA helpers (baseline PTX, works on sm_103) =========
__device__ __forceinline__ uint32_t smem_to_u32(const void* p) {
    uint32_t a;
    asm("{ .reg .u64 t; cvta.to.shared.u64 t, %1; cvt.u32.u64 %0, t; }"
        : "=r"(a) : "l"(p));
    return a;
}

__device__ __forceinline__ void ldsm_x4(uint32_t addr, uint32_t* r) {
    asm volatile("ldmatrix.sync.aligned.m8n8.x4.shared.b16 {%0,%1,%2,%3}, [%4];"
                 : "=r"(r[0]), "=r"(r[1]), "=r"(r[2]), "=r"(r[3]) : "r"(addr));
}

__device__ __forceinline__ void mma_bf16(float* d, const uint32_t* a,
                                         const uint32_t* b) {
    asm volatile(
        "mma.sync.aligned.m16n8k16.row.col.f32.bf16.bf16.f32 "
        "{%0,%1,%2,%3}, {%4,%5,%6,%7}, {%8,%9}, {%0,%1,%2,%3};"
        : "+f"(d[0]), "+f"(d[1]), "+f"(d[2]), "+f"(d[3])
        : "r"(a[0]), "r"(a[1]), "r"(a[2]), "r"(a[3]), "r"(b[0]), "r"(b[1]));
}

// ================= bf16-split GEMM via mma.sync ==============================
// C[M,N] = A[M,K] @ B[N,K]^T, fp32 in/out. A,B row-major with leading dim K.
// Split: v = hi(bf16) + lo(bf16); acc += Ah*Bh + Ah*Bl + Al*Bh (fp32 accum).
// EPI: 0 plain, 1 exact gelu, 2 residual add
#define KC 32
#define ROWB 128                 // bytes per smem row: 32 bf16 hi | 32 bf16 lo
#define TILE_B (128 * ROWB)      // 16 KB per matrix tile
#define STAGE_B (2 * TILE_B)     // A + B per stage
#define GEMM_SMEM (2 * STAGE_B)  // double buffer = 64 KB

template <int EPI>
__global__ void __launch_bounds__(256)
mma_gemm(int M, int N, int K,
         const float* __restrict__ A, const float* __restrict__ B,
         const float* __restrict__ RES, float* __restrict__ C) {
    extern __shared__ char smem[];
    const uint32_t smem_u32 = smem_to_u32(smem);

    const int t = threadIdx.x;
    const int lane = t & 31;
    const int wid = t >> 5;
    const int wm = wid & 3;        // warp m index (0..3) -> 32 rows each
    const int wn = wid >> 2;       // warp n index (0..1) -> 64 cols each
    const int m0 = blockIdx.y * 128;
    const int n0 = blockIdx.x * 128;

    // ---- staging loads: thread handles row (t>>1), 16 cols at half (t&1) ----
    const int lrow = t >> 1;
    const int lhalf = t & 1;
    const float* Ag = A + (size_t)(m0 + lrow) * K + lhalf * 16;
    const float* Bg = B + (size_t)(n0 + lrow) * K + lhalf * 16;

    float4 ra[4], rb[4];

    auto LDG_chunk = [&](int k0) {
        #pragma unroll
        for (int i = 0; i < 4; i++) {
            ra[i] = *reinterpret_cast<const float4*>(Ag + k0 + i * 4);
            rb[i] = *reinterpret_cast<const float4*>(Bg + k0 + i * 4);
        }
    };

    auto STS_chunk = [&](int s) {
        char* stA = smem + s * STAGE_B;
        char* stB = stA + TILE_B;
        const uint32_t rowbase = (uint32_t)lrow * ROWB;
        const uint32_t sw = (uint32_t)(lrow & 7) << 4;
        #pragma unroll
        for (int i = 0; i < 4; i++) {
            const uint32_t offh = (uint32_t)(lhalf * 32 + i * 8);
            {
                float4 v = ra[i];
                __nv_bfloat162 h01 = __floats2bfloat162_rn(v.x, v.y);
                __nv_bfloat162 h23 = __floats2bfloat162_rn(v.z, v.w);
                __nv_bfloat162 l01 = __floats2bfloat162_rn(
                    v.x - __bfloat162float(h01.x), v.y - __bfloat162float(h01.y));
                __nv_bfloat162 l23 = __floats2bfloat162_rn(
                    v.z - __bfloat162float(h23.x), v.w - __bfloat162float(h23.y));
                uint2 hv = make_uint2(*reinterpret_cast<uint32_t*>(&h01),
                                      *reinterpret_cast<uint32_t*>(&h23));
                uint2 lv = make_uint2(*reinterpret_cast<uint32_t*>(&l01),
                                      *reinterpret_cast<uint32_t*>(&l23));
                *reinterpret_cast<uint2*>(stA + rowbase + (offh ^ sw)) = hv;
                *reinterpret_cast<uint2*>(stA + rowbase + ((offh + 64) ^ sw)) = lv;
            }
            {
                float4 v = rb[i];
                __nv_bfloat162 h01 = __floats2bfloat162_rn(v.x, v.y);
                __nv_bfloat162 h23 = __floats2bfloat162_rn(v.z, v.w);
                __nv_bfloat162 l01 = __floats2bfloat162_rn(
                    v.x - __bfloat162float(h01.x), v.y - __bfloat162float(h01.y));
                __nv_bfloat162 l23 = __floats2bfloat162_rn(
                    v.z - __bfloat162float(h23.x), v.w - __bfloat162float(h23.y));
                uint2 hv = make_uint2(*reinterpret_cast<uint32_t*>(&h01),
                                      *reinterpret_cast<uint32_t*>(&h23));
                uint2 lv = make_uint2(*reinterpret_cast<uint32_t*>(&l01),
                                      *reinterpret_cast<uint32_t*>(&l23));
                *reinterpret_cast<uint2*>(stB + rowbase + (offh ^ sw)) = hv;
                *reinterpret_cast<uint2*>(stB + rowbase + ((offh + 64) ^ sw)) = lv;
            }
        }
    };

    float acc[2][8][4];
    #pragma unroll
    for (int mt = 0; mt < 2; mt++)
        #pragma unroll
        for (int nt = 0; nt < 8; nt++)
            #pragma unroll
            for (int j = 0; j < 4; j++) acc[mt][nt][j] = 0.f;

    const int nch = K / KC;

    // prologue
    LDG_chunk(0);
    STS_chunk(0);
    __syncthreads();

    const int lrow16 = lane & 15;
    const int cg = (lane >> 4) & 1;

    for (int i = 0; i < nch; i++) {
        const int s = i & 1;
        if (i + 1 < nch) LDG_chunk((i + 1) * KC);

        const uint32_t sA = smem_u32 + s * STAGE_B;
        const uint32_t sB = sA + TILE_B;

        #pragma unroll
        for (int ks = 0; ks < 2; ks++) {
            const uint32_t cbh = (uint32_t)(ks * 32 + cg * 16);
            uint32_t Ah[2][4], Al[2][4];
            #pragma unroll
            for (int mt = 0; mt < 2; mt++) {
                const int row = wm * 32 + mt * 16 + lrow16;
                const uint32_t swz = (uint32_t)(row & 7) << 4;
                const uint32_t base = sA + (uint32_t)row * ROWB;
                ldsm_x4(base + (cbh ^ swz), Ah[mt]);
                ldsm_x4(base + ((cbh + 64) ^ swz), Al[mt]);
            }
            #pragma unroll
            for (int q = 0; q < 4; q++) {
                const int row = wn * 64 + q * 16 + lrow16;
                const uint32_t swz = (uint32_t)(row & 7) << 4;
                const uint32_t base = sB + (uint32_t)row * ROWB;
                uint32_t rh[4], rl[4];
                ldsm_x4(base + (cbh ^ swz), rh);
                ldsm_x4(base + ((cbh + 64) ^ swz), rl);
                uint32_t bh0[2] = {rh[0], rh[2]};
                uint32_t bh1[2] = {rh[1], rh[3]};
                uint32_t bl0[2] = {rl[0], rl[2]};
                uint32_t bl1[2] = {rl[1], rl[3]};
                #pragma unroll
                for (int mt = 0; mt < 2; mt++) {
                    mma_bf16(acc[mt][2 * q + 0], Ah[mt], bh0);
                    mma_bf16(acc[mt][2 * q + 0], Ah[mt], bl0);
                    mma_bf16(acc[mt][2 * q + 0], Al[mt], bh0);
                    mma_bf16(acc[mt][2 * q + 1], Ah[mt], bh1);
                    mma_bf16(acc[mt][2 * q + 1], Ah[mt], bl1);
                    mma_bf16(acc[mt][2 * q + 1], Al[mt], bh1);
                }
            }
        }

        __syncthreads();
        if (i + 1 < nch) {
            STS_chunk((i + 1) & 1);
            __syncthreads();
        }
    }

    // ---- epilogue: thread owns 2 cols x (2 m-tiles x 8 n-tiles x 2 rowgrps) ----
    const int er0 = m0 + wm * 32 + (lane >> 2);
    const int ec0 = n0 + wn * 64 + (lane & 3) * 2;
    #pragma unroll
    for (int mt = 0; mt < 2; mt++) {
        #pragma unroll
        for (int g = 0; g < 2; g++) {
            const int row = er0 + mt * 16 + g * 8;
            #pragma unroll
            for (int nt = 0; nt < 8; nt++) {
                const int col = ec0 + nt * 8;
                float v0 = acc[mt][nt][g * 2 + 0];
                float v1 = acc[mt][nt][g * 2 + 1];
                size_t roff = (size_t)row * N + col;
                if (EPI == 1) {
                    v0 = 0.5f * v0 * (1.0f + erff(v0 * 0.70710678118654752f));
                    v1 = 0.5f * v1 * (1.0f + erff(v1 * 0.70710678118654752f));
                } else if (EPI == 2) {
                    float2 r = *reinterpret_cast<const float2*>(RES + roff);
                    v0 += r.x;
                    v1 += r.y;
                }
                *reinterpret_cast<float2*>(C + roff) = make_float2(v0, v1);
            }
        }
    }
}

// ---------------- RMSNorm ---------------------------------------------------
__global__ void rmsnorm_kernel(const float* __restrict__ x,
                               const float* __restrict__ w,
                               float* __restrict__ out) {
    int row = blockIdx.x;
    const float4* xr = reinterpret_cast<const float4*>(x + (size_t)row * D_MODEL);
    const float4* w4 = reinterpret_cast<const float4*>(w);
    float4* o4 = reinterpret_cast<float4*>(out + (size_t)row * D_MODEL);

    float ss = 0.f;
    for (int i = threadIdx.x; i < D_MODEL / 4; i += blockDim.x) {
        float4 v = xr[i];
        ss += v.x * v.x + v.y * v.y + v.z * v.z + v.w * v.w;
    }
    for (int off = 16; off > 0; off >>= 1)
        ss += __shfl_xor_sync(0xFFFFFFFFu, ss, off);

    __shared__ float red[8];
    __shared__ float s_rms;
    int lane = threadIdx.x & 31, wid = threadIdx.x >> 5;
    if (lane == 0) red[wid] = ss;
    __syncthreads();
    if (threadIdx.x == 0) {
        float tt = 0.f;
        #pragma unroll
        for (int i = 0; i < 8; i++) tt += red[i];
        s_rms = rsqrtf(tt / (float)D_MODEL + 1e-6f);
    }
    __syncthreads();
    float r = s_rms;
    for (int i = threadIdx.x; i < D_MODEL / 4; i += blockDim.x) {
        float4 v = xr[i];
        float4 ww = w4[i];
        o4[i] = make_float4(v.x * r * ww.x, v.y * r * ww.y,
                            v.z * r * ww.z, v.w * r * ww.w);
    }
}

// ---------------- Flash attention (fp32, causal, key mask) ------------------
#define BQ 64
#define BKV 64
#define SS_LD 65

#define FA_SMEM_FLOATS (3 * BQ * HEAD_DIM + BQ * SS_LD + 3 * BQ)
#define FA_SMEM_BYTES  (FA_SMEM_FLOATS * 4)

__global__ void __launch_bounds__(256)
flash_attn_kernel(const float* __restrict__ Q, const float* __restrict__ K,
                  const float* __restrict__ V, const int* __restrict__ mask,
                  float* __restrict__ O) {
    extern __shared__ float sm[];
    float* Qs = sm;
    float* Ks = Qs + BQ * HEAD_DIM;
    float* Vs = Ks + BQ * HEAD_DIM;
    float* Ss = Vs + BQ * HEAD_DIM;
    float* m_s = Ss + BQ * SS_LD;
    float* l_s = m_s + BQ;
    float* alpha_s = l_s + BQ;

    int qi = blockIdx.x;
    int h  = blockIdx.y;
    int b  = blockIdx.z;
    int t  = threadIdx.x;
    int tx = t & 15, ty = t >> 4;
    int q0 = qi * BQ;
    size_t base = (size_t)b * SEQ * D_MODEL + (size_t)h * HEAD_DIM;
    const int* bmask = mask + b * SEQ;
    const float scale = 0.08838834764831845f;

    for (int i = t; i < BQ * (HEAD_DIM / 4); i += 256) {
        int r = i >> 5, c4 = i & 31;
        reinterpret_cast<float4*>(Qs)[i] = *reinterpret_cast<const float4*>(
            Q + base + (size_t)(q0 + r) * D_MODEL + c4 * 4);
    }
    if (t < BQ) { m_s[t] = -3.0e38f; l_s[t] = 0.f; }

    float acc[4][8];
    #pragma unroll
    for (int r = 0; r < 4; r++)
        #pragma unroll
        for (int c = 0; c < 8; c++) acc[r][c] = 0.f;

    for (int j = 0; j <= qi; ++j) {
        int k0 = j * BKV;
        __syncthreads();
        for (int i = t; i < BKV * (HEAD_DIM / 4); i += 256) {
            int r = i >> 5, c4 = i & 31;
            size_t goff = base + (size_t)(k0 + r) * D_MODEL + c4 * 4;
            reinterpret_cast<float4*>(Ks)[i] = *reinterpret_cast<const float4*>(K + goff);
            reinterpret_cast<float4*>(Vs)[i] = *reinterpret_cast<const float4*>(V + goff);
        }
        __syncthreads();

        float s[4][4];
        #pragma unroll
        for (int r = 0; r < 4; r++)
            #pragma unroll
            for (int c = 0; c < 4; c++) s[r][c] = 0.f;

        for (int d = 0; d < HEAD_DIM; d += 4) {
            float4 qv[4], kv[4];
            #pragma unroll
            for (int r = 0; r < 4; r++)
                qv[r] = *reinterpret_cast<const float4*>(&Qs[(ty * 4 + r) * HEAD_DIM + d]);
            #pragma unroll
            for (int c = 0; c < 4; c++)
                kv[c] = *reinterpret_cast<const float4*>(&Ks[(tx * 4 + c) * HEAD_DIM + d]);
            #pragma unroll
            for (int r = 0; r < 4; r++)
                #pragma unroll
                for (int c = 0; c < 4; c++)
                    s[r][c] += qv[r].x * kv[c].x + qv[r].y * kv[c].y +
                               qv[r].z * kv[c].z + qv[r].w * kv[c].w;
        }

        bool diag = (j == qi);
        #pragma unroll
        for (int r = 0; r < 4; r++) {
            int qg = q0 + ty * 4 + r;
            #pragma unroll
            for (int c = 0; c < 4; c++) {
                int kg = k0 + tx * 4 + c;
                float v = s[r][c] * scale;
                if ((diag && kg > qg) || bmask[kg] == 0) v = -1e9f;
                Ss[(ty * 4 + r) * SS_LD + tx * 4 + c] = v;
            }
        }
        __syncthreads();

        {
            int row = t >> 2, part = t & 3;
            float* srow = &Ss[row * SS_LD + part * 16];
            float vals[16];
            float mx = -3.0e38f;
            #pragma unroll
            for (int i2 = 0; i2 < 16; i2++) { vals[i2] = srow[i2]; mx = fmaxf(mx, vals[i2]); }
            mx = fmaxf(mx, __shfl_xor_sync(0xFFFFFFFFu, mx, 1));
            mx = fmaxf(mx, __shfl_xor_sync(0xFFFFFFFFu, mx, 2));
            float m_old = m_s[row];
            float m_new = fmaxf(m_old, mx);
            float sum = 0.f;
            #pragma unroll
            for (int i2 = 0; i2 < 16; i2++) {
                float p = expf(vals[i2] - m_new);
                srow[i2] = p;
                sum += p;
            }
            sum += __shfl_xor_sync(0xFFFFFFFFu, sum, 1);
            sum += __shfl_xor_sync(0xFFFFFFFFu, sum, 2);
            if (part == 0) {
                float al = expf(m_old - m_new);
                alpha_s[row] = al;
                l_s[row] = l_s[row] * al + sum;
                m_s[row] = m_new;
            }
        }
        __syncthreads();

        {
            float al[4];
            #pragma unroll
            for (int r = 0; r < 4; r++) al[r] = alpha_s[ty * 4 + r];
            #pragma unroll
            for (int r = 0; r < 4; r++)
                #pragma unroll
                for (int c = 0; c < 8; c++) acc[r][c] *= al[r];

            for (int k = 0; k < BKV; k++) {
                float4 v0 = *reinterpret_cast<const float4*>(&Vs[k * HEAD_DIM + tx * 8]);
                float4 v1 = *reinterpret_cast<const float4*>(&Vs[k * HEAD_DIM + tx * 8 + 4]);
                #pragma unroll
                for (int r = 0; r < 4; r++) {
                    float p = Ss[(ty * 4 + r) * SS_LD + k];
                    acc[r][0] = fmaf(p, v0.x, acc[r][0]);
                    acc[r][1] = fmaf(p, v0.y, acc[r][1]);
                    acc[r][2] = fmaf(p, v0.z, acc[r][2]);
                    acc[r][3] = fmaf(p, v0.w, acc[r][3]);
                    acc[r][4] = fmaf(p, v1.x, acc[r][4]);
                    acc[r][5] = fmaf(p, v1.y, acc[r][5]);
                    acc[r][6] = fmaf(p, v1.z, acc[r][6]);
                    acc[r][7] = fmaf(p, v1.w, acc[r][7]);
                }
            }
        }
    }
    __syncthreads();

    #pragma unroll
    for (int r = 0; r < 4; r++) {
        int row = ty * 4 + r;
        float l = l_s[row];
        float inv = (l > 0.f) ? (1.f / l) : 0.f;
        size_t ooff = base + (size_t)(q0 + row) * D_MODEL + tx * 8;
        *reinterpret_cast<float4*>(O + ooff) =
            make_float4(acc[r][0] * inv, acc[r][1] * inv, acc[r][2] * inv, acc[r][3] * inv);
        *reinterpret_cast<float4*>(O + ooff + 4) =
            make_float4(acc[r][4] * inv, acc[r][5] * inv, acc[r][6] * inv, acc[r][7] * inv);
    }
}

// ---------------- launch -----------------------------------------------------
extern "C" void kernel_launch(void* const* d_in, const int* in_sizes, int n_in,
                              void* d_out, int out_size) {
    const float* x           = (const float*)d_in[0];
    const int*   attn_mask   = (const int*)  d_in[1];
    const float* w_norm_attn = (const float*)d_in[2];
    const float* wq          = (const float*)d_in[3];
    const float* wk          = (const float*)d_in[4];
    const float* wv          = (const float*)d_in[5];
    const float* wo          = (const float*)d_in[6];
    const float* w_norm_mlp  = (const float*)d_in[7];
    const float* w_up        = (const float*)d_in[8];
    const float* w_down      = (const float*)d_in[9];
    float* out = (float*)d_out;

    float *h, *q, *k, *v, *att, *x1, *up;
    cudaGetSymbolAddress((void**)&h,   g_h);
    cudaGetSymbolAddress((void**)&q,   g_q);
    cudaGetSymbolAddress((void**)&k,   g_k);
    cudaGetSymbolAddress((void**)&v,   g_v);
    cudaGetSymbolAddress((void**)&att, g_att);
    cudaGetSymbolAddress((void**)&x1,  g_x1);
    cudaGetSymbolAddress((void**)&up,  g_up);

    cudaFuncSetAttribute(flash_attn_kernel,
                         cudaFuncAttributeMaxDynamicSharedMemorySize, FA_SMEM_BYTES);
    cudaFuncSetAttribute(mma_gemm<0>,
                         cudaFuncAttributeMaxDynamicSharedMemorySize, GEMM_SMEM);
    cudaFuncSetAttribute(mma_gemm<1>,
                         cudaFuncAttributeMaxDynamicSharedMemorySize, GEMM_SMEM);
    cudaFuncSetAttribute(mma_gemm<2>,
                         cudaFuncAttributeMaxDynamicSharedMemorySize, GEMM_SMEM);

    // 1) rmsnorm(x) -> h
    rmsnorm_kernel<<<TOK, 256>>>(x, w_norm_attn, h);

    // 2) q, k, v projections (tensor-core mma.sync, bf16 split)
    dim3 gD(D_MODEL / 128, TOK / 128);
    mma_gemm<0><<<gD, 256, GEMM_SMEM>>>(TOK, D_MODEL, D_MODEL, h, wq, nullptr, q);
    mma_gemm<0><<<gD, 256, GEMM_SMEM>>>(TOK, D_MODEL, D_MODEL, h, wk, nullptr, k);
    mma_gemm<0><<<gD, 256, GEMM_SMEM>>>(TOK, D_MODEL, D_MODEL, h, wv, nullptr, v);

    // 3) attention (fp32 flash)
    dim3 gA(SEQ / BQ, N_HEADS, BATCH);
    flash_attn_kernel<<<gA, 256, FA_SMEM_BYTES>>>(q, k, v, attn_mask, att);

    // 4) output projection + residual -> x1
    mma_gemm<2><<<gD, 256, GEMM_SMEM>>>(TOK, D_MODEL, D_MODEL, att, wo, x, x1);

    // 5) rmsnorm(x1) -> h
    rmsnorm_kernel<<<TOK, 256>>>(x1, w_norm_mlp, h);

    // 6) up projection + exact gelu -> up
    dim3 gU(MLP_DIM / 128, TOK / 128);
    mma_gemm<1><<<gU, 256, GEMM_SMEM>>>(TOK, MLP_DIM, D_MODEL, h, w_up, nullptr, up);

    // 7) down projection + residual -> out
    mma_gemm<2><<<gD, 256, GEMM_SMEM>>>(TOK, D_MODEL, MLP_DIM, up, w_down, x1, out);
}

// round 4
// speedup vs baseline: 2.0815x; 1.3797x over previous
#include <cuda_runtime.h>
#include <cuda_bf16.h>
#include <math.h>
#include <stdint.h>

#define D_MODEL 2048
#define N_HEADS 16
#define HEAD_DIM 128
#define MLP_DIM 8192
#define BATCH 2
#define SEQ 2048
#define TOK (BATCH * SEQ)

// ---------------- scratch (static device globals; no allocation allowed) ----
__device__ float g_h[(size_t)TOK * D_MODEL];
__device__ float g_q[(size_t)TOK * D_MODEL];
__device__ float g_k[(size_t)TOK * D_MODEL];
__device__ float g_v[(size_t)TOK * D_MODEL];
__device__ float g_att[(size_t)TOK * D_MODEL];
__device__ float g_x1[(size_t)TOK * D_MODEL];
__device__ float g_up[(size_t)TOK * MLP_DIM];

// ================= warp-MMA helpers (baseline PTX, works on sm_103) =========
__device__ __forceinline__ uint32_t smem_to_u32(const void* p) {
    uint32_t a;
    asm("{ .reg .u64 t; cvta.to.shared.u64 t, %1; cvt.u32.u64 %0, t; }"
        : "=r"(a) : "l"(p));
    return a;
}

__device__ __forceinline__ void ldsm_x4(uint32_t addr, uint32_t* r) {
    asm volatile("ldmatrix.sync.aligned.m8n8.x4.shared.b16 {%0,%1,%2,%3}, [%4];"
                 : "=r"(r[0]), "=r"(r[1]), "=r"(r[2]), "=r"(r[3]) : "r"(addr));
}

__device__ __forceinline__ void mma_bf16(float* d, const uint32_t* a,
                                         const uint32_t* b) {
    asm volatile(
        "mma.sync.aligned.m16n8k16.row.col.f32.bf16.bf16.f32 "
        "{%0,%1,%2,%3}, {%4,%5,%6,%7}, {%8,%9}, {%0,%1,%2,%3};"
        : "+f"(d[0]), "+f"(d[1]), "+f"(d[2]), "+f"(d[3])
        : "r"(a[0]), "r"(a[1]), "r"(a[2]), "r"(a[3]), "r"(b[0]), "r"(b[1]));
}

__device__ __forceinline__ uint32_t bf2_bits(__nv_bfloat162 v) {
    return *reinterpret_cast<uint32_t*>(&v);
}

// ================= bf16-split GEMM via mma.sync ==============================
#define KC 32
#define ROWB 128
#define TILE_B (128 * ROWB)
#define STAGE_B (2 * TILE_B)
#define GEMM_SMEM (2 * STAGE_B)

template <int EPI>
__global__ void __launch_bounds__(256)
mma_gemm(int M, int N, int K,
         const float* __restrict__ A, const float* __restrict__ B,
         const float* __restrict__ RES, float* __restrict__ C) {
    extern __shared__ char smem[];
    const uint32_t smem_u32 = smem_to_u32(smem);

    const int t = threadIdx.x;
    const int lane = t & 31;
    const int wid = t >> 5;
    const int wm = wid & 3;
    const int wn = wid >> 2;
    const int m0 = blockIdx.y * 128;
    const int n0 = blockIdx.x * 128;

    const int lrow = t >> 1;
    const int lhalf = t & 1;
    const float* Ag = A + (size_t)(m0 + lrow) * K + lhalf * 16;
    const float* Bg = B + (size_t)(n0 + lrow) * K + lhalf * 16;

    float4 ra[4], rb[4];

    auto LDG_chunk = [&](int k0) {
        #pragma unroll
        for (int i = 0; i < 4; i++) {
            ra[i] = *reinterpret_cast<const float4*>(Ag + k0 + i * 4);
            rb[i] = *reinterpret_cast<const float4*>(Bg + k0 + i * 4);
        }
    };

    auto STS_chunk = [&](int s) {
        char* stA = smem + s * STAGE_B;
        char* stB = stA + TILE_B;
        const uint32_t rowbase = (uint32_t)lrow * ROWB;
        const uint32_t sw = (uint32_t)(lrow & 7) << 4;
        #pragma unroll
        for (int i = 0; i < 4; i++) {
            const uint32_t offh = (uint32_t)(lhalf * 32 + i * 8);
            {
                float4 v = ra[i];
                __nv_bfloat162 h01 = __floats2bfloat162_rn(v.x, v.y);
                __nv_bfloat162 h23 = __floats2bfloat162_rn(v.z, v.w);
                __nv_bfloat162 l01 = __floats2bfloat162_rn(
                    v.x - __bfloat162float(h01.x), v.y - __bfloat162float(h01.y));
                __nv_bfloat162 l23 = __floats2bfloat162_rn(
                    v.z - __bfloat162float(h23.x), v.w - __bfloat162float(h23.y));
                *reinterpret_cast<uint2*>(stA + rowbase + (offh ^ sw)) =
                    make_uint2(bf2_bits(h01), bf2_bits(h23));
                *reinterpret_cast<uint2*>(stA + rowbase + ((offh + 64) ^ sw)) =
                    make_uint2(bf2_bits(l01), bf2_bits(l23));
            }
            {
                float4 v = rb[i];
                __nv_bfloat162 h01 = __floats2bfloat162_rn(v.x, v.y);
                __nv_bfloat162 h23 = __floats2bfloat162_rn(v.z, v.w);
                __nv_bfloat162 l01 = __floats2bfloat162_rn(
                    v.x - __bfloat162float(h01.x), v.y - __bfloat162float(h01.y));
                __nv_bfloat162 l23 = __floats2bfloat162_rn(
                    v.z - __bfloat162float(h23.x), v.w - __bfloat162float(h23.y));
                *reinterpret_cast<uint2*>(stB + rowbase + (offh ^ sw)) =
                    make_uint2(bf2_bits(h01), bf2_bits(h23));
                *reinterpret_cast<uint2*>(stB + rowbase + ((offh + 64) ^ sw)) =
                    make_uint2(bf2_bits(l01), bf2_bits(l23));
            }
        }
    };

    float acc[2][8][4];
    #pragma unroll
    for (int mt = 0; mt < 2; mt++)
        #pragma unroll
        for (int nt = 0; nt < 8; nt++)
            #pragma unroll
            for (int j = 0; j < 4; j++) acc[mt][nt][j] = 0.f;

    const int nch = K / KC;

    LDG_chunk(0);
    STS_chunk(0);
    __syncthreads();

    const int lrow16 = lane & 15;
    const int cg = (lane >> 4) & 1;

    for (int i = 0; i < nch; i++) {
        const int s = i & 1;
        if (i + 1 < nch) LDG_chunk((i + 1) * KC);

        const uint32_t sA = smem_u32 + s * STAGE_B;
        const uint32_t sB = sA + TILE_B;

        #pragma unroll
        for (int ks = 0; ks < 2; ks++) {
            const uint32_t cbh = (uint32_t)(ks * 32 + cg * 16);
            uint32_t Ah[2][4], Al[2][4];
            #pragma unroll
            for (int mt = 0; mt < 2; mt++) {
                const int row = wm * 32 + mt * 16 + lrow16;
                const uint32_t swz = (uint32_t)(row & 7) << 4;
                const uint32_t base = sA + (uint32_t)row * ROWB;
                ldsm_x4(base + (cbh ^ swz), Ah[mt]);
                ldsm_x4(base + ((cbh + 64) ^ swz), Al[mt]);
            }
            #pragma unroll
            for (int q = 0; q < 4; q++) {
                const int row = wn * 64 + q * 16 + lrow16;
                const uint32_t swz = (uint32_t)(row & 7) << 4;
                const uint32_t base = sB + (uint32_t)row * ROWB;
                uint32_t rh[4], rl[4];
                ldsm_x4(base + (cbh ^ swz), rh);
                ldsm_x4(base + ((cbh + 64) ^ swz), rl);
                uint32_t bh0[2] = {rh[0], rh[2]};
                uint32_t bh1[2] = {rh[1], rh[3]};
                uint32_t bl0[2] = {rl[0], rl[2]};
                uint32_t bl1[2] = {rl[1], rl[3]};
                #pragma unroll
                for (int mt = 0; mt < 2; mt++) {
                    mma_bf16(acc[mt][2 * q + 0], Ah[mt], bh0);
                    mma_bf16(acc[mt][2 * q + 0], Ah[mt], bl0);
                    mma_bf16(acc[mt][2 * q + 0], Al[mt], bh0);
                    mma_bf16(acc[mt][2 * q + 1], Ah[mt], bh1);
                    mma_bf16(acc[mt][2 * q + 1], Ah[mt], bl1);
                    mma_bf16(acc[mt][2 * q + 1], Al[mt], bh1);
                }
            }
        }

        if (i + 1 < nch) STS_chunk((i + 1) & 1);
        __syncthreads();
    }

    const int er0 = m0 + wm * 32 + (lane >> 2);
    const int ec0 = n0 + wn * 64 + (lane & 3) * 2;
    #pragma unroll
    for (int mt = 0; mt < 2; mt++) {
        #pragma unroll
        for (int g = 0; g < 2; g++) {
            const int row = er0 + mt * 16 + g * 8;
            #pragma unroll
            for (int nt = 0; nt < 8; nt++) {
                const int col = ec0 + nt * 8;
                float v0 = acc[mt][nt][g * 2 + 0];
                float v1 = acc[mt][nt][g * 2 + 1];
                size_t roff = (size_t)row * N + col;
                if (EPI == 1) {
                    v0 = 0.5f * v0 * (1.0f + erff(v0 * 0.70710678118654752f));
                    v1 = 0.5f * v1 * (1.0f + erff(v1 * 0.70710678118654752f));
                } else if (EPI == 2) {
                    float2 r = *reinterpret_cast<const float2*>(RES + roff);
                    v0 += r.x;
                    v1 += r.y;
                }
                *reinterpret_cast<float2*>(C + roff) = make_float2(v0, v1);
            }
        }
    }
}

// ================= tensor-core flash attention (bf16 split) ==================
// BQ=128 rows/CTA (8 warps x 16), KV chunk 64. Double-buffered K/Vt staging;
// buffer 1 recycles the Q staging region (Q fragments live in registers).
// smem layout (bytes):
//   buf1 / Q:  [0, 65536)        K: hi 0..16K, lo 16K..32K | Vt: hi 32K..48K, lo 48K..64K
//              (Q staging: hi [0,32K), lo [32K,64K))
//   buf0:      [65536, 131072)   same sublayout
//   mask:      [131072, +512)    2 slots x 64 ints
#define ATT_BUF0 65536
#define ATT_MASK 131072
#define ATT_SMEM_BYTES (131072 + 512)

__device__ __forceinline__ void att_stage_chunk(
    char* smem, uint32_t bufoff, const float* __restrict__ Kg,
    const float* __restrict__ Vg, const int* __restrict__ bm,
    int kv0, int slot, int t) {
    // K tile: 64 rows x 128 d -> rows of 256B (hi), +16384 (lo)
    {
        const int row = t >> 2;
        const int dq = (t & 3) * 32;
        const float4* g = reinterpret_cast<const float4*>(
            Kg + (size_t)(kv0 + row) * D_MODEL + dq);
        char* kh = smem + bufoff + (uint32_t)row * 256;
        const uint32_t sw = (uint32_t)(row & 7) << 4;
        #pragma unroll
        for (int i = 0; i < 8; i++) {
            float4 v = g[i];
            __nv_bfloat162 h01 = __floats2bfloat162_rn(v.x, v.y);
            __nv_bfloat162 h23 = __floats2bfloat162_rn(v.z, v.w);
            __nv_bfloat162 l01 = __floats2bfloat162_rn(
                v.x - __bfloat162float(h01.x), v.y - __bfloat162float(h01.y));
            __nv_bfloat162 l23 = __floats2bfloat162_rn(
                v.z - __bfloat162float(h23.x), v.w - __bfloat162float(h23.y));
            const uint32_t off = ((uint32_t)(dq * 2 + i * 8)) ^ sw;
            *reinterpret_cast<uint2*>(kh + off) =
                make_uint2(bf2_bits(h01), bf2_bits(h23));
            *reinterpret_cast<uint2*>(kh + 16384 + off) =
                make_uint2(bf2_bits(l01), bf2_bits(l23));
        }
    }
    // Vt tile: transpose V[kv][d] -> Vt[d][kv]: 128 rows x 64 kv, 128B rows
    {
        const int kvp = t & 31;
        const int dblk = t >> 5;
        const float4* g0 = reinterpret_cast<const float4*>(
            Vg + (size_t)(kv0 + 2 * kvp) * D_MODEL + dblk * 16);
        const float4* g1 = reinterpret_cast<const float4*>(
            Vg + (size_t)(kv0 + 2 * kvp + 1) * D_MODEL + dblk * 16);
        #pragma unroll
        for (int dd = 0; dd < 4; dd++) {
            float4 a = g0[dd], b = g1[dd];
            float av[4] = {a.x, a.y, a.z, a.w};
            float bv[4] = {b.x, b.y, b.z, b.w};
            #pragma unroll
            for (int e = 0; e < 4; e++) {
                const int d = dblk * 16 + dd * 4 + e;
                __nv_bfloat162 hh = __floats2bfloat162_rn(av[e], bv[e]);
                __nv_bfloat162 ll = __floats2bfloat162_rn(
                    av[e] - __bfloat162float(hh.x), bv[e] - __bfloat162float(hh.y));
                const uint32_t off =
                    ((uint32_t)(kvp * 4)) ^ ((uint32_t)(d & 7) << 4);
                char* vrow = smem + bufoff + 32768 + (uint32_t)d * 128;
                *reinterpret_cast<uint32_t*>(vrow + off) = bf2_bits(hh);
                *reinterpret_cast<uint32_t*>(vrow + 16384 + off) = bf2_bits(ll);
            }
        }
    }
    if (t < 64)
        reinterpret_cast<int*>(smem + ATT_MASK + slot * 256)[t] = bm[kv0 + t];
}

__global__ void __launch_bounds__(256, 1)
flash_attn_tc(const float* __restrict__ Q, const float* __restrict__ K,
              const float* __restrict__ V, const int* __restrict__ mask,
              float* __restrict__ O) {
    extern __shared__ char smem[];
    const uint32_t sb = smem_to_u32(smem);
    const int t = threadIdx.x, lane = t & 31, w = t >> 5;
    const int qi = blockIdx.x, h = blockIdx.y, b = blockIdx.z;
    const int q0 = qi * 128;
    const size_t base = (size_t)b * SEQ * D_MODEL + (size_t)h * HEAD_DIM;
    const int* bm = mask + b * SEQ;
    const float scale = 0.08838834764831845f;  // 1/sqrt(128)

    // ---- stage Q (hi [0,32K), lo [32K,64K)) ----
    {
        const int row = t >> 1, half = t & 1;
        const float4* g = reinterpret_cast<const float4*>(
            Q + base + (size_t)(q0 + row) * D_MODEL + half * 64);
        char* qh = smem + (uint32_t)row * 256;
        const uint32_t sw = (uint32_t)(row & 7) << 4;
        #pragma unroll
        for (int i = 0; i < 16; i++) {
            float4 v = g[i];
            __nv_bfloat162 h01 = __floats2bfloat162_rn(v.x, v.y);
            __nv_bfloat162 h23 = __floats2bfloat162_rn(v.z, v.w);
            __nv_bfloat162 l01 = __floats2bfloat162_rn(
                v.x - __bfloat162float(h01.x), v.y - __bfloat162float(h01.y));
            __nv_bfloat162 l23 = __floats2bfloat162_rn(
                v.z - __bfloat162float(h23.x), v.w - __bfloat162float(h23.y));
            const uint32_t off = ((uint32_t)(half * 128 + i * 8)) ^ sw;
            *reinterpret_cast<uint2*>(qh + off) =
                make_uint2(bf2_bits(h01), bf2_bits(h23));
            *reinterpret_cast<uint2*>(qh + 32768 + off) =
                make_uint2(bf2_bits(l01), bf2_bits(l23));
        }
    }
    __syncthreads();

    // ---- preload Q fragments (constant across all KV chunks) ----
    uint32_t Ah[8][4], Al[8][4];
    {
        const int r = w * 16 + (lane & 15);
        const uint32_t swz = (uint32_t)(r & 7) << 4;
        const uint32_t cg = ((uint32_t)(lane >> 4)) << 4;
        const uint32_t qb = sb + (uint32_t)r * 256;
        #pragma unroll
        for (int ds = 0; ds < 8; ds++) {
            const uint32_t off = (((uint32_t)(ds * 32)) + cg) ^ swz;
            ldsm_x4(qb + off, Ah[ds]);
            ldsm_x4(qb + 32768 + off, Al[ds]);
        }
    }
    att_stage_chunk(smem, ATT_BUF0, K + base, V + base, bm, 0, 0, t);
    __syncthreads();

    float m1 = -1e30f, l1 = 0.f, m2 = -1e30f, l2 = 0.f;
    float acc[16][4];
    #pragma unroll
    for (int nt = 0; nt < 16; nt++)
        #pragma unroll
        for (int c = 0; c < 4; c++) acc[nt][c] = 0.f;

    const int r1g = q0 + w * 16 + (lane >> 2);
    const int r2g = r1g + 8;
    const int nch = 2 * qi + 2;
    const uint32_t cg = ((uint32_t)(lane >> 4)) << 4;

    for (int j = 0; j < nch; j++) {
        const int s = j & 1;
        const uint32_t bufo = s ? 0u : (uint32_t)ATT_BUF0;
        const int kv0 = j * 64;

        // ---- scores S = Q K^T (3-pass split) ----
        float sacc[8][4];
        #pragma unroll
        for (int nt = 0; nt < 8; nt++)
            #pragma unroll
            for (int c = 0; c < 4; c++) sacc[nt][c] = 0.f;

        #pragma unroll
        for (int g4 = 0; g4 < 4; g4++) {
            const int kr = g4 * 16 + (lane & 15);
            const uint32_t swz = (uint32_t)(kr & 7) << 4;
            const uint32_t kb = sb + bufo + (uint32_t)kr * 256;
            #pragma unroll
            for (int ds = 0; ds < 8; ds++) {
                const uint32_t off = (((uint32_t)(ds * 32)) + cg) ^ swz;
                uint32_t rh[4], rl[4];
                ldsm_x4(kb + off, rh);
                ldsm_x4(kb + 16384 + off, rl);
                uint32_t bh0[2] = {rh[0], rh[2]}, bh1[2] = {rh[1], rh[3]};
                uint32_t bl0[2] = {rl[0], rl[2]}, bl1[2] = {rl[1], rl[3]};
                mma_bf16(sacc[2 * g4 + 0], Ah[ds], bh0);
                mma_bf16(sacc[2 * g4 + 0], Ah[ds], bl0);
                mma_bf16(sacc[2 * g4 + 0], Al[ds], bh0);
                mma_bf16(sacc[2 * g4 + 1], Ah[ds], bh1);
                mma_bf16(sacc[2 * g4 + 1], Ah[ds], bl1);
                mma_bf16(sacc[2 * g4 + 1], Al[ds], bh1);
            }
        }

        // ---- scale + causal + key mask ----
        const int* mrow = reinterpret_cast<const int*>(smem + ATT_MASK + s * 256);
        #pragma unroll
        for (int nt = 0; nt < 8; nt++) {
            const int c0 = nt * 8 + (lane & 3) * 2;
            const int k0g = kv0 + c0, k1g = k0g + 1;
            const bool mv0 = mrow[c0] != 0, mv1 = mrow[c0 + 1] != 0;
            float v0 = sacc[nt][0] * scale, v1 = sacc[nt][1] * scale;
            float v2 = sacc[nt][2] * scale, v3 = sacc[nt][3] * scale;
            sacc[nt][0] = (k0g > r1g || !mv0) ? -1e9f : v0;
            sacc[nt][1] = (k1g > r1g || !mv1) ? -1e9f : v1;
            sacc[nt][2] = (k0g > r2g || !mv0) ? -1e9f : v2;
            sacc[nt][3] = (k1g > r2g || !mv1) ? -1e9f : v3;
        }

        // ---- online softmax ----
        float mx1 = -1e30f, mx2 = -1e30f;
        #pragma unroll
        for (int nt = 0; nt < 8; nt++) {
            mx1 = fmaxf(mx1, fmaxf(sacc[nt][0], sacc[nt][1]));
            mx2 = fmaxf(mx2, fmaxf(sacc[nt][2], sacc[nt][3]));
        }
        mx1 = fmaxf(mx1, __shfl_xor_sync(0xFFFFFFFFu, mx1, 1));
        mx1 = fmaxf(mx1, __shfl_xor_sync(0xFFFFFFFFu, mx1, 2));
        mx2 = fmaxf(mx2, __shfl_xor_sync(0xFFFFFFFFu, mx2, 1));
        mx2 = fmaxf(mx2, __shfl_xor_sync(0xFFFFFFFFu, mx2, 2));
        const float m1n = fmaxf(m1, mx1), m2n = fmaxf(m2, mx2);
        const float a1 = __expf(m1 - m1n), a2 = __expf(m2 - m2n);
        float s1 = 0.f, s2 = 0.f;
        #pragma unroll
        for (int nt = 0; nt < 8; nt++) {
            sacc[nt][0] = __expf(sacc[nt][0] - m1n);
            sacc[nt][1] = __expf(sacc[nt][1] - m1n);
            sacc[nt][2] = __expf(sacc[nt][2] - m2n);
            sacc[nt][3] = __expf(sacc[nt][3] - m2n);
            s1 += sacc[nt][0] + sacc[nt][1];
            s2 += sacc[nt][2] + sacc[nt][3];
        }
        s1 += __shfl_xor_sync(0xFFFFFFFFu, s1, 1);
        s1 += __shfl_xor_sync(0xFFFFFFFFu, s1, 2);
        s2 += __shfl_xor_sync(0xFFFFFFFFu, s2, 1);
        s2 += __shfl_xor_sync(0xFFFFFFFFu, s2, 2);
        l1 = l1 * a1 + s1; m1 = m1n;
        l2 = l2 * a2 + s2; m2 = m2n;
        #pragma unroll
        for (int nt = 0; nt < 16; nt++) {
            acc[nt][0] *= a1; acc[nt][1] *= a1;
            acc[nt][2] *= a2; acc[nt][3] *= a2;
        }

        // ---- O += P V (3-pass split; P frags built from score C frags) ----
        #pragma unroll
        for (int ks = 0; ks < 4; ks++) {
            const float* p0 = sacc[2 * ks];
            const float* p1 = sacc[2 * ks + 1];
            __nv_bfloat162 h0 = __floats2bfloat162_rn(p0[0], p0[1]);
            __nv_bfloat162 h1 = __floats2bfloat162_rn(p0[2], p0[3]);
            __nv_bfloat162 h2 = __floats2bfloat162_rn(p1[0], p1[1]);
            __nv_bfloat162 h3 = __floats2bfloat162_rn(p1[2], p1[3]);
            uint32_t pa_h[4] = {bf2_bits(h0), bf2_bits(h1), bf2_bits(h2), bf2_bits(h3)};
            __nv_bfloat162 e0 = __floats2bfloat162_rn(
                p0[0] - __bfloat162float(h0.x), p0[1] - __bfloat162float(h0.y));
            __nv_bfloat162 e1 = __floats2bfloat162_rn(
                p0[2] - __bfloat162float(h1.x), p0[3] - __bfloat162float(h1.y));
            __nv_bfloat162 e2 = __floats2bfloat162_rn(
                p1[0] - __bfloat162float(h2.x), p1[1] - __bfloat162float(h2.y));
            __nv_bfloat162 e3 = __floats2bfloat162_rn(
                p1[2] - __bfloat162float(h3.x), p1[3] - __bfloat162float(h3.y));
            uint32_t pa_l[4] = {bf2_bits(e0), bf2_bits(e1), bf2_bits(e2), bf2_bits(e3)};

            #pragma unroll
            for (int gd = 0; gd < 8; gd++) {
                const int dr = gd * 16 + (lane & 15);
                const uint32_t swz = (uint32_t)(dr & 7) << 4;
                const uint32_t off = (((uint32_t)(ks * 32)) + cg) ^ swz;
                const uint32_t vb = sb + bufo + 32768 + (uint32_t)dr * 128;
                uint32_t rh[4], rl[4];
                ldsm_x4(vb + off, rh);
                ldsm_x4(vb + 16384 + off, rl);
                uint32_t bh0[2] = {rh[0], rh[2]}, bh1[2] = {rh[1], rh[3]};
                uint32_t bl0[2] = {rl[0], rl[2]}, bl1[2] = {rl[1], rl[3]};
                mma_bf16(acc[2 * gd + 0], pa_h, bh0);
                mma_bf16(acc[2 * gd + 0], pa_h, bl0);
                mma_bf16(acc[2 * gd + 0], pa_l, bh0);
                mma_bf16(acc[2 * gd + 1], pa_h, bh1);
                mma_bf16(acc[2 * gd + 1], pa_h, bl1);
                mma_bf16(acc[2 * gd + 1], pa_l, bh1);
            }
        }

        if (j + 1 < nch)
            att_stage_chunk(smem, (j & 1) ? (uint32_t)ATT_BUF0 : 0u,
                            K + base, V + base, bm, kv0 + 64, (j + 1) & 1, t);
        __syncthreads();
    }

    // ---- epilogue ----
    const float i1 = (l1 > 0.f) ? 1.f / l1 : 0.f;
    const float i2 = (l2 > 0.f) ? 1.f / l2 : 0.f;
    #pragma unroll
    for (int nt = 0; nt < 16; nt++) {
        const int col = nt * 8 + (lane & 3) * 2;
        *reinterpret_cast<float2*>(O + base + (size_t)r1g * D_MODEL + col) =
            make_float2(acc[nt][0] * i1, acc[nt][1] * i1);
        *reinterpret_cast<float2*>(O + base + (size_t)r2g * D_MODEL + col) =
            make_float2(acc[nt][2] * i2, acc[nt][3] * i2);
    }
}

// ---------------- RMSNorm ---------------------------------------------------
__global__ void rmsnorm_kernel(const float* __restrict__ x,
                               const float* __restrict__ w,
                               float* __restrict__ out) {
    int row = blockIdx.x;
    const float4* xr = reinterpret_cast<const float4*>(x + (size_t)row * D_MODEL);
    const float4* w4 = reinterpret_cast<const float4*>(w);
    float4* o4 = reinterpret_cast<float4*>(out + (size_t)row * D_MODEL);

    float ss = 0.f;
    for (int i = threadIdx.x; i < D_MODEL / 4; i += blockDim.x) {
        float4 v = xr[i];
        ss += v.x * v.x + v.y * v.y + v.z * v.z + v.w * v.w;
    }
    for (int off = 16; off > 0; off >>= 1)
        ss += __shfl_xor_sync(0xFFFFFFFFu, ss, off);

    __shared__ float red[8];
    __shared__ float s_rms;
    int lane = threadIdx.x & 31, wid = threadIdx.x >> 5;
    if (lane == 0) red[wid] = ss;
    __syncthreads();
    if (threadIdx.x == 0) {
        float tt = 0.f;
        #pragma unroll
        for (int i = 0; i < 8; i++) tt += red[i];
        s_rms = rsqrtf(tt / (float)D_MODEL + 1e-6f);
    }
    __syncthreads();
    float r = s_rms;
    for (int i = threadIdx.x; i < D_MODEL / 4; i += blockDim.x) {
        float4 v = xr[i];
        float4 ww = w4[i];
        o4[i] = make_float4(v.x * r * ww.x, v.y * r * ww.y,
                            v.z * r * ww.z, v.w * r * ww.w);
    }
}

// ---------------- launch -----------------------------------------------------
extern "C" void kernel_launch(void* const* d_in, const int* in_sizes, int n_in,
                              void* d_out, int out_size) {
    const float* x           = (const float*)d_in[0];
    const int*   attn_mask   = (const int*)  d_in[1];
    const float* w_norm_attn = (const float*)d_in[2];
    const float* wq          = (const float*)d_in[3];
    const float* wk          = (const float*)d_in[4];
    const float* wv          = (const float*)d_in[5];
    const float* wo          = (const float*)d_in[6];
    const float* w_norm_mlp  = (const float*)d_in[7];
    const float* w_up        = (const float*)d_in[8];
    const float* w_down      = (const float*)d_in[9];
    float* out = (float*)d_out;

    float *h, *q, *k, *v, *att, *x1, *up;
    cudaGetSymbolAddress((void**)&h,   g_h);
    cudaGetSymbolAddress((void**)&q,   g_q);
    cudaGetSymbolAddress((void**)&k,   g_k);
    cudaGetSymbolAddress((void**)&v,   g_v);
    cudaGetSymbolAddress((void**)&att, g_att);
    cudaGetSymbolAddress((void**)&x1,  g_x1);
    cudaGetSymbolAddress((void**)&up,  g_up);

    cudaFuncSetAttribute(flash_attn_tc,
                         cudaFuncAttributeMaxDynamicSharedMemorySize, ATT_SMEM_BYTES);
    cudaFuncSetAttribute(mma_gemm<0>,
                         cudaFuncAttributeMaxDynamicSharedMemorySize, GEMM_SMEM);
    cudaFuncSetAttribute(mma_gemm<1>,
                         cudaFuncAttributeMaxDynamicSharedMemorySize, GEMM_SMEM);
    cudaFuncSetAttribute(mma_gemm<2>,
                         cudaFuncAttributeMaxDynamicSharedMemorySize, GEMM_SMEM);

    // 1) rmsnorm(x) -> h
    rmsnorm_kernel<<<TOK, 256>>>(x, w_norm_attn, h);

    // 2) q, k, v projections
    dim3 gD(D_MODEL / 128, TOK / 128);
    mma_gemm<0><<<gD, 256, GEMM_SMEM>>>(TOK, D_MODEL, D_MODEL, h, wq, nullptr, q);
    mma_gemm<0><<<gD, 256, GEMM_SMEM>>>(TOK, D_MODEL, D_MODEL, h, wk, nullptr, k);
    mma_gemm<0><<<gD, 256, GEMM_SMEM>>>(TOK, D_MODEL, D_MODEL, h, wv, nullptr, v);

    // 3) attention (tensor-core flash, bf16 split)
    dim3 gA(SEQ / 128, N_HEADS, BATCH);
    flash_attn_tc<<<gA, 256, ATT_SMEM_BYTES>>>(q, k, v, attn_mask, att);

    // 4) output projection + residual -> x1
    mma_gemm<2><<<gD, 256, GEMM_SMEM>>>(TOK, D_MODEL, D_MODEL, att, wo, x, x1);

    // 5) rmsnorm(x1) -> h
    rmsnorm_kernel<<<TOK, 256>>>(x1, w_norm_mlp, h);

    // 6) up projection + exact gelu -> up
    dim3 gU(MLP_DIM / 128, TOK / 128);
    mma_gemm<1><<<gU, 256, GEMM_SMEM>>>(TOK, MLP_DIM, D_MODEL, h, w_up, nullptr, up);

    // 7) down projection + residual -> out
    mma_gemm<2><<<gD, 256, GEMM_SMEM>>>(TOK, D_MODEL, MLP_DIM, up, w_down, x1, out);
}